// round 13
// baseline (speedup 1.0000x reference)
#include <cuda_runtime.h>
#include <cuda_bf16.h>
#include <cuda_fp8.h>
#include <cstdint>

#define B_ROWS 8192
#define F_DIM 128
#define Q_DIM 64
#define IN_DIM 193
#define H1D 256
#define H2D 256
#define THRESH 0.95f
#define EPSV 1e-12f

#define KT 768   // 3 segments of 256 cols

// Scratch (no allocations allowed)
__device__ uint32_t g_xn8[B_ROWS * 32];                      // normalized rows, e4m3 packed
__device__ int   g_cnt[B_ROWS];
__device__ __align__(16) __nv_bfloat16 g_fpp[B_ROWS * KT];   // [fh|fh|fl]
__device__ __align__(16) __nv_bfloat16 g_w1pp[H1D * KT];     // [wh|wl|wh]
__device__ __align__(16) __nv_bfloat16 g_hpp[B_ROWS * KT];   // [hh|hh|hl]
__device__ __align__(16) __nv_bfloat16 g_w2pp[H2D * KT];     // [wh|wl|wh]
__device__ float g_part[B_ROWS * 8];                          // layer3 partials: [row][tile*4+warp_n]

__device__ __forceinline__ uint32_t smem_u32(const void* p) {
    uint32_t a;
    asm("{ .reg .u64 t; cvta.to.shared.u64 t, %1; cvt.u32.u64 %0, t; }" : "=r"(a) : "l"(p));
    return a;
}
#define SWZ256(b)  ((b) ^ ((((b) >> 8) & 7) << 4))
#define SWZ128B(b) ((b) ^ ((((b) >> 7) & 7) << 4))

// ---------------------------------------------------------------------------
// Kernel 1: row L2 norm -> e4m3 normalized rows (packed); zero counters
// ---------------------------------------------------------------------------
__global__ void rownorm_kernel(const float* __restrict__ x) {
    int row  = blockIdx.x * 8 + (threadIdx.x >> 5);
    int lane = threadIdx.x & 31;
    const float4* xr = (const float4*)(x + (size_t)row * F_DIM);
    float4 v = xr[lane];
    float s = v.x * v.x + v.y * v.y + v.z * v.z + v.w * v.w;
    #pragma unroll
    for (int o = 16; o > 0; o >>= 1) s += __shfl_xor_sync(0xffffffffu, s, o);
    float inv = 1.0f / (sqrtf(s) + EPSV);
    uint32_t p =  (uint32_t)__nv_cvt_float_to_fp8(v.x * inv, __NV_SATFINITE, __NV_E4M3)
               | ((uint32_t)__nv_cvt_float_to_fp8(v.y * inv, __NV_SATFINITE, __NV_E4M3) << 8)
               | ((uint32_t)__nv_cvt_float_to_fp8(v.z * inv, __NV_SATFINITE, __NV_E4M3) << 16)
               | ((uint32_t)__nv_cvt_float_to_fp8(v.w * inv, __NV_SATFINITE, __NV_E4M3) << 24);
    g_xn8[(size_t)row * 32 + lane] = p;
    if (lane == 0) g_cnt[row] = 0;
}

// ---------------------------------------------------------------------------
// Kernel 2: symmetric gram-count, fp8 e4m3 mma.sync (m16n8k32, 2x HMMA rate).
// ---------------------------------------------------------------------------
#define GRAM_SMEM_DYN 32768

__global__ void __launch_bounds__(256) gram_mma_kernel() {
    int bi = blockIdx.y, bj = blockIdx.x;
    if (bj < bi) return;
    const bool diag = (bi == bj);

    extern __shared__ char smem[];
    int t = threadIdx.x, wid = t >> 5, lane = t & 31;
    int warp_m = wid >> 2, warp_n = wid & 3;
    int rowBase = bi * 128;
    int colBase = bj * 128;

    uint32_t sA = smem_u32(smem);
    uint32_t sB = sA + 16384;

    #pragma unroll
    for (int l = 0; l < 4; l++) {
        int u = t + l * 256;
        int row = u >> 3, seg = u & 7;
        uint4 va = ((const uint4*)g_xn8)[(size_t)(rowBase + row) * 8 + seg];
        uint4 vb = ((const uint4*)g_xn8)[(size_t)(colBase + row) * 8 + seg];
        uint32_t off = SWZ128B((uint32_t)row * 128 + seg * 16);
        *(uint4*)(smem + off)         = va;
        *(uint4*)(smem + 16384 + off) = vb;
    }
    __syncthreads();

    int a_row_l   = warp_m * 64 + (lane & 15);
    int a_chunk_l = lane >> 4;
    int b_row_l   = warp_n * 32 + ((lane >> 4) << 3) + (lane & 7);
    int b_chunk_l = (lane >> 3) & 1;

    float acc[4][4][4];
    #pragma unroll
    for (int mi = 0; mi < 4; mi++)
        #pragma unroll
        for (int ni = 0; ni < 4; ni++)
            #pragma unroll
            for (int r = 0; r < 4; r++) acc[mi][ni][r] = 0.0f;

    #pragma unroll
    for (int kk = 0; kk < 4; kk++) {
        uint32_t a[4][4];
        #pragma unroll
        for (int mi = 0; mi < 4; mi++) {
            uint32_t byte = (uint32_t)(a_row_l + mi * 16) * 128 + (kk * 2 + a_chunk_l) * 16;
            uint32_t addr = sA + SWZ128B(byte);
            asm volatile("ldmatrix.sync.aligned.m8n8.x4.shared.b16 {%0,%1,%2,%3}, [%4];"
                         : "=r"(a[mi][0]), "=r"(a[mi][1]), "=r"(a[mi][2]), "=r"(a[mi][3])
                         : "r"(addr));
        }
        uint32_t b[4][2];
        #pragma unroll
        for (int np = 0; np < 2; np++) {
            uint32_t byte = (uint32_t)(b_row_l + np * 16) * 128 + (kk * 2 + b_chunk_l) * 16;
            uint32_t addr = sB + SWZ128B(byte);
            asm volatile("ldmatrix.sync.aligned.m8n8.x4.shared.b16 {%0,%1,%2,%3}, [%4];"
                         : "=r"(b[np*2][0]), "=r"(b[np*2][1]), "=r"(b[np*2+1][0]), "=r"(b[np*2+1][1])
                         : "r"(addr));
        }
        #pragma unroll
        for (int mi = 0; mi < 4; mi++)
            #pragma unroll
            for (int ni = 0; ni < 4; ni++)
                asm volatile(
                    "mma.sync.aligned.m16n8k32.row.col.f32.e4m3.e4m3.f32 "
                    "{%0,%1,%2,%3}, {%4,%5,%6,%7}, {%8,%9}, {%0,%1,%2,%3};"
                    : "+f"(acc[mi][ni][0]), "+f"(acc[mi][ni][1]),
                      "+f"(acc[mi][ni][2]), "+f"(acc[mi][ni][3])
                    : "r"(a[mi][0]), "r"(a[mi][1]), "r"(a[mi][2]), "r"(a[mi][3]),
                      "r"(b[ni][0]), "r"(b[ni][1]));
    }

    int g0 = lane >> 2, q4 = lane & 3;
    #pragma unroll
    for (int mi = 0; mi < 4; mi++) {
        int row0 = rowBase + warp_m * 64 + mi * 16 + g0;
        int row1 = row0 + 8;
        #pragma unroll
        for (int ni = 0; ni < 4; ni++) {
            int c0 = colBase + warp_n * 32 + ni * 8 + q4 * 2;
            #pragma unroll
            for (int r = 0; r < 4; r++) {
                int row = (r < 2) ? row0 : row1;
                int col = c0 + (r & 1);
                float v = acc[mi][ni][r];
                if (v * v >= THRESH && row != col) {
                    atomicAdd(&g_cnt[row], 1);
                    if (!diag) atomicAdd(&g_cnt[col], 1);
                }
            }
        }
    }
}

// ---------------------------------------------------------------------------
// Prep: split-bf16 feats, vectorized (bf162). 2 rows per CTA. [hi|hi|lo]
// ---------------------------------------------------------------------------
__global__ void prep_feats_kernel(const float* __restrict__ x,
                                  const float* __restrict__ q) {
    int t = threadIdx.x;
    int row = blockIdx.x * 2 + (t >> 7);
    int k2 = t & 127;
    int k = k2 * 2;
    float f0 = 0.0f, f1 = 0.0f;
    if (k < F_DIM) {
        float2 v = *(const float2*)(x + (size_t)row * F_DIM + k);
        f0 = v.x; f1 = v.y;
    } else if (k < F_DIM + Q_DIM) {
        float2 v = *(const float2*)(q + (size_t)row * Q_DIM + (k - F_DIM));
        f0 = v.x; f1 = v.y;
    } else if (k == IN_DIM - 1) {
        f0 = (float)g_cnt[row] * (1.0f / (float)B_ROWS);
    }
    __nv_bfloat16 h0 = __float2bfloat16_rn(f0), h1 = __float2bfloat16_rn(f1);
    __nv_bfloat162 hi(h0, h1);
    __nv_bfloat162 lo(__float2bfloat16_rn(f0 - __bfloat162float(h0)),
                      __float2bfloat16_rn(f1 - __bfloat162float(h1)));
    __nv_bfloat162* base = (__nv_bfloat162*)(g_fpp + (size_t)row * KT);
    base[k2]       = hi;
    base[128 + k2] = hi;
    base[256 + k2] = lo;
}

__global__ void prep_w_kernel(const float* __restrict__ W1,
                              const float* __restrict__ W2) {
    int n = blockIdx.x;
    int k = threadIdx.x;
    {
        float f = (k < IN_DIM) ? W1[(size_t)n * IN_DIM + k] : 0.0f;
        __nv_bfloat16 hi = __float2bfloat16_rn(f);
        __nv_bfloat16 lo = __float2bfloat16_rn(f - __bfloat162float(hi));
        size_t base = (size_t)n * KT;
        g_w1pp[base + k]       = hi;
        g_w1pp[base + 256 + k] = lo;
        g_w1pp[base + 512 + k] = hi;
    }
    {
        float f = W2[(size_t)n * H1D + k];
        __nv_bfloat16 hi = __float2bfloat16_rn(f);
        __nv_bfloat16 lo = __float2bfloat16_rn(f - __bfloat162float(hi));
        size_t base = (size_t)n * KT;
        g_w2pp[base + k]       = hi;
        g_w2pp[base + 256 + k] = lo;
        g_w2pp[base + 512 + k] = hi;
    }
}

// ---------------------------------------------------------------------------
// MLP GEMM (HMMA): K=768 in 6 chunks. MODE 0 -> split h; MODE 1 -> fused
// layer3 partials, one slot per (row, col-tile, warp_n): no races.
// ---------------------------------------------------------------------------
#define MLP_SMEM_DYN 65536

template <int MODE>
__global__ void __launch_bounds__(256) mlp_mma_kernel(const float* __restrict__ bias,
                                                      const float* __restrict__ W3) {
    const __nv_bfloat16* A = (MODE == 0) ? g_fpp  : g_hpp;
    const __nv_bfloat16* W = (MODE == 0) ? g_w1pp : g_w2pp;

    extern __shared__ char smem[];
    int t = threadIdx.x, wid = t >> 5, lane = t & 31;
    int warp_m = wid >> 2, warp_n = wid & 3;
    int mBase = blockIdx.y * 128;
    int nBase = blockIdx.x * 128;

    uint32_t sA = smem_u32(smem);
    uint32_t sB = sA + 32768;

    int a_row_l   = warp_m * 64 + (lane & 15);
    int a_chunk_l = lane >> 4;
    int b_row_l   = warp_n * 32 + ((lane >> 4) << 3) + (lane & 7);
    int b_chunk_l = (lane >> 3) & 1;

    float acc[4][4][4];
    #pragma unroll
    for (int mi = 0; mi < 4; mi++)
        #pragma unroll
        for (int ni = 0; ni < 4; ni++)
            #pragma unroll
            for (int r = 0; r < 4; r++) acc[mi][ni][r] = 0.0f;

    for (int c = 0; c < KT / 128; c++) {
        if (c) __syncthreads();
        #pragma unroll
        for (int l = 0; l < 8; l++) {
            int u = t + l * 256;
            int row = u >> 4, seg = u & 15;
            const char* pa = (const char*)A + (size_t)(mBase + row) * (KT * 2) + c * 256 + seg * 16;
            const char* pw = (const char*)W + (size_t)(nBase + row) * (KT * 2) + c * 256 + seg * 16;
            uint32_t off = SWZ256((uint32_t)row * 256 + seg * 16);
            *(uint4*)(smem + off)         = *(const uint4*)pa;
            *(uint4*)(smem + 32768 + off) = *(const uint4*)pw;
        }
        __syncthreads();

        #pragma unroll
        for (int kk = 0; kk < 8; kk++) {
            uint32_t a[4][4];
            #pragma unroll
            for (int mi = 0; mi < 4; mi++) {
                uint32_t byte = (uint32_t)(a_row_l + mi * 16) * 256 + (kk * 2 + a_chunk_l) * 16;
                uint32_t addr = sA + SWZ256(byte);
                asm volatile("ldmatrix.sync.aligned.m8n8.x4.shared.b16 {%0,%1,%2,%3}, [%4];"
                             : "=r"(a[mi][0]), "=r"(a[mi][1]), "=r"(a[mi][2]), "=r"(a[mi][3])
                             : "r"(addr));
            }
            uint32_t b[4][2];
            #pragma unroll
            for (int np = 0; np < 2; np++) {
                uint32_t byte = (uint32_t)(b_row_l + np * 16) * 256 + (kk * 2 + b_chunk_l) * 16;
                uint32_t addr = sB + SWZ256(byte);
                asm volatile("ldmatrix.sync.aligned.m8n8.x4.shared.b16 {%0,%1,%2,%3}, [%4];"
                             : "=r"(b[np*2][0]), "=r"(b[np*2][1]), "=r"(b[np*2+1][0]), "=r"(b[np*2+1][1])
                             : "r"(addr));
            }
            #pragma unroll
            for (int mi = 0; mi < 4; mi++)
                #pragma unroll
                for (int ni = 0; ni < 4; ni++)
                    asm volatile(
                        "mma.sync.aligned.m16n8k16.row.col.f32.bf16.bf16.f32 "
                        "{%0,%1,%2,%3}, {%4,%5,%6,%7}, {%8,%9}, {%0,%1,%2,%3};"
                        : "+f"(acc[mi][ni][0]), "+f"(acc[mi][ni][1]),
                          "+f"(acc[mi][ni][2]), "+f"(acc[mi][ni][3])
                        : "r"(a[mi][0]), "r"(a[mi][1]), "r"(a[mi][2]), "r"(a[mi][3]),
                          "r"(b[ni][0]), "r"(b[ni][1]));
        }
    }

    int g0 = lane >> 2, q4 = lane & 3;
    #pragma unroll
    for (int mi = 0; mi < 4; mi++) {
        int row0 = mBase + warp_m * 64 + mi * 16 + g0;
        int row1 = row0 + 8;
        float s0 = 0.0f, s1 = 0.0f;
        #pragma unroll
        for (int ni = 0; ni < 4; ni++) {
            int col = nBase + warp_n * 32 + ni * 8 + q4 * 2;
            float bv0 = bias[col], bv1 = bias[col + 1];
            float h00 = fmaxf(acc[mi][ni][0] + bv0, 0.0f);
            float h01 = fmaxf(acc[mi][ni][1] + bv1, 0.0f);
            float h10 = fmaxf(acc[mi][ni][2] + bv0, 0.0f);
            float h11 = fmaxf(acc[mi][ni][3] + bv1, 0.0f);
            if (MODE == 0) {
                __nv_bfloat16 a0 = __float2bfloat16_rn(h00), a1 = __float2bfloat16_rn(h01);
                __nv_bfloat16 c0 = __float2bfloat16_rn(h10), c1 = __float2bfloat16_rn(h11);
                __nv_bfloat162 hi0(a0, a1), hi1(c0, c1);
                __nv_bfloat162 lo0(__float2bfloat16_rn(h00 - __bfloat162float(a0)),
                                   __float2bfloat16_rn(h01 - __bfloat162float(a1)));
                __nv_bfloat162 lo1(__float2bfloat16_rn(h10 - __bfloat162float(c0)),
                                   __float2bfloat16_rn(h11 - __bfloat162float(c1)));
                __nv_bfloat162* p0 = (__nv_bfloat162*)(g_hpp + (size_t)row0 * KT + col);
                __nv_bfloat162* p1 = (__nv_bfloat162*)(g_hpp + (size_t)row1 * KT + col);
                p0[0] = hi0; p0[128] = hi0; p0[256] = lo0;
                p1[0] = hi1; p1[128] = hi1; p1[256] = lo1;
            } else {
                float w0 = W3[col], w1 = W3[col + 1];
                s0 = fmaf(h00, w0, fmaf(h01, w1, s0));
                s1 = fmaf(h10, w0, fmaf(h11, w1, s1));
            }
        }
        if (MODE == 1) {
            s0 += __shfl_xor_sync(0xffffffffu, s0, 1);
            s0 += __shfl_xor_sync(0xffffffffu, s0, 2);
            s1 += __shfl_xor_sync(0xffffffffu, s1, 1);
            s1 += __shfl_xor_sync(0xffffffffu, s1, 2);
            if (q4 == 0) {
                int slot = blockIdx.x * 4 + warp_n;          // 8 slots per row
                g_part[(size_t)row0 * 8 + slot] = s0;
                g_part[(size_t)row1 * 8 + slot] = s1;
            }
        }
    }
}

// ---------------------------------------------------------------------------
// Finalize: out[row] = sum of 8 partials + b3 (deterministic fold).
// One warp per 4 rows: lane i handles row = base + (i>>3), slot = i&7.
// Simpler: 256 threads, each thread sums 8 consecutive floats.
// ---------------------------------------------------------------------------
__global__ void finalize_kernel(const float* __restrict__ b3,
                                float* __restrict__ out) {
    int i = blockIdx.x * 256 + threadIdx.x;
    const float4* p = (const float4*)(g_part + (size_t)i * 8);
    float4 u = p[0], v = p[1];
    out[i] = ((u.x + u.y) + (u.z + u.w)) + ((v.x + v.y) + (v.z + v.w)) + b3[0];
}

// ---------------------------------------------------------------------------
extern "C" void kernel_launch(void* const* d_in, const int* in_sizes, int n_in,
                              void* d_out, int out_size) {
    const float* x  = (const float*)d_in[0];
    const float* q  = (const float*)d_in[1];
    const float* W1 = (const float*)d_in[2];
    const float* b1 = (const float*)d_in[3];
    const float* W2 = (const float*)d_in[4];
    const float* b2 = (const float*)d_in[5];
    const float* W3 = (const float*)d_in[6];
    const float* b3 = (const float*)d_in[7];
    float* out = (float*)d_out;

    cudaFuncSetAttribute(gram_mma_kernel,
                         cudaFuncAttributeMaxDynamicSharedMemorySize, GRAM_SMEM_DYN);
    cudaFuncSetAttribute(mlp_mma_kernel<0>,
                         cudaFuncAttributeMaxDynamicSharedMemorySize, MLP_SMEM_DYN);
    cudaFuncSetAttribute(mlp_mma_kernel<1>,
                         cudaFuncAttributeMaxDynamicSharedMemorySize, MLP_SMEM_DYN);

    rownorm_kernel<<<B_ROWS / 8, 256>>>(x);
    prep_w_kernel<<<256, 256>>>(W1, W2);
    gram_mma_kernel<<<dim3(B_ROWS / 128, B_ROWS / 128), 256, GRAM_SMEM_DYN>>>();
    prep_feats_kernel<<<B_ROWS / 2, 256>>>(x, q);
    mlp_mma_kernel<0><<<dim3(H1D / 128, B_ROWS / 128), 256, MLP_SMEM_DYN>>>(b1, W3);
    mlp_mma_kernel<1><<<dim3(H2D / 128, B_ROWS / 128), 256, MLP_SMEM_DYN>>>(b2, W3);
    finalize_kernel<<<B_ROWS / 256, 256>>>(b3, out);
}

// round 14
// speedup vs baseline: 1.1896x; 1.1896x over previous
#include <cuda_runtime.h>
#include <cuda_bf16.h>
#include <cstdint>

#define B_ROWS 8192
#define F_DIM 128
#define Q_DIM 64
#define IN_DIM 193
#define H1D 256
#define H2D 256
#define THRESH 0.95f
#define EPSV 1e-12f

#define KT 768   // 3 segments of 256 cols

// Scratch (no allocations allowed)
__device__ __align__(16) __nv_bfloat16 g_xnb[B_ROWS * F_DIM]; // normalized rows, bf16
__device__ int   g_cnt[B_ROWS];
__device__ __align__(16) __nv_bfloat16 g_fpp[B_ROWS * KT];   // [fh|fh|fl]
__device__ __align__(16) __nv_bfloat16 g_w1pp[H1D * KT];     // [wh|wl|wh]
__device__ __align__(16) __nv_bfloat16 g_hpp[B_ROWS * KT];   // [hh|hh|hl]
__device__ __align__(16) __nv_bfloat16 g_w2pp[H2D * KT];     // [wh|wl|wh]
__device__ float g_part[B_ROWS * 8];                          // layer3 partials: [row][tile*4+warp_n]

__device__ __forceinline__ uint32_t smem_u32(const void* p) {
    uint32_t a;
    asm("{ .reg .u64 t; cvta.to.shared.u64 t, %1; cvt.u32.u64 %0, t; }" : "=r"(a) : "l"(p));
    return a;
}
#define SWZ256(b) ((b) ^ ((((b) >> 8) & 7) << 4))

// ---------------------------------------------------------------------------
// Kernel 1: row L2 norm -> bf16 normalized rows; zero counters (proven R11)
// ---------------------------------------------------------------------------
__global__ void rownorm_kernel(const float* __restrict__ x) {
    int row  = blockIdx.x * 8 + (threadIdx.x >> 5);
    int lane = threadIdx.x & 31;
    const float4* xr = (const float4*)(x + (size_t)row * F_DIM);
    float4 v = xr[lane];
    float s = v.x * v.x + v.y * v.y + v.z * v.z + v.w * v.w;
    #pragma unroll
    for (int o = 16; o > 0; o >>= 1) s += __shfl_xor_sync(0xffffffffu, s, o);
    float inv = 1.0f / (sqrtf(s) + EPSV);
    __nv_bfloat162* outp = (__nv_bfloat162*)(g_xnb + (size_t)row * F_DIM);
    outp[lane * 2 + 0] = __nv_bfloat162(__float2bfloat16_rn(v.x * inv), __float2bfloat16_rn(v.y * inv));
    outp[lane * 2 + 1] = __nv_bfloat162(__float2bfloat16_rn(v.z * inv), __float2bfloat16_rn(v.w * inv));
    if (lane == 0) g_cnt[row] = 0;
}

// ---------------------------------------------------------------------------
// Kernel 2: symmetric gram-count, bf16 HMMA (proven R11 — fp8 mma.sync is
// emulated/slow on sm_103 non-'a' target, measured 2.3x slower in R13).
// ---------------------------------------------------------------------------
#define GRAM_SMEM_DYN 65536

__global__ void __launch_bounds__(256) gram_mma_kernel() {
    int bi = blockIdx.y, bj = blockIdx.x;
    if (bj < bi) return;
    const bool diag = (bi == bj);

    extern __shared__ char smem[];
    int t = threadIdx.x, wid = t >> 5, lane = t & 31;
    int warp_m = wid >> 2, warp_n = wid & 3;
    int rowBase = bi * 128;
    int colBase = bj * 128;

    uint32_t sA = smem_u32(smem);
    uint32_t sB = sA + 32768;

    #pragma unroll
    for (int l = 0; l < 8; l++) {
        int u = t + l * 256;
        int row = u >> 4, seg = u & 15;
        uint4 va = ((const uint4*)(g_xnb + (size_t)(rowBase + row) * F_DIM))[seg];
        uint4 vb = ((const uint4*)(g_xnb + (size_t)(colBase + row) * F_DIM))[seg];
        uint32_t off = SWZ256((uint32_t)row * 256 + seg * 16);
        *(uint4*)(smem + off)         = va;
        *(uint4*)(smem + 32768 + off) = vb;
    }
    __syncthreads();

    int a_row_l   = warp_m * 64 + (lane & 15);
    int a_chunk_l = lane >> 4;
    int b_row_l   = warp_n * 32 + ((lane >> 4) << 3) + (lane & 7);
    int b_chunk_l = (lane >> 3) & 1;

    float acc[4][4][4];
    #pragma unroll
    for (int mi = 0; mi < 4; mi++)
        #pragma unroll
        for (int ni = 0; ni < 4; ni++)
            #pragma unroll
            for (int r = 0; r < 4; r++) acc[mi][ni][r] = 0.0f;

    #pragma unroll
    for (int kk = 0; kk < 8; kk++) {
        uint32_t a[4][4];
        #pragma unroll
        for (int mi = 0; mi < 4; mi++) {
            uint32_t byte = (uint32_t)(a_row_l + mi * 16) * 256 + (kk * 2 + a_chunk_l) * 16;
            uint32_t addr = sA + SWZ256(byte);
            asm volatile("ldmatrix.sync.aligned.m8n8.x4.shared.b16 {%0,%1,%2,%3}, [%4];"
                         : "=r"(a[mi][0]), "=r"(a[mi][1]), "=r"(a[mi][2]), "=r"(a[mi][3])
                         : "r"(addr));
        }
        uint32_t b[4][2];
        #pragma unroll
        for (int np = 0; np < 2; np++) {
            uint32_t byte = (uint32_t)(b_row_l + np * 16) * 256 + (kk * 2 + b_chunk_l) * 16;
            uint32_t addr = sB + SWZ256(byte);
            asm volatile("ldmatrix.sync.aligned.m8n8.x4.shared.b16 {%0,%1,%2,%3}, [%4];"
                         : "=r"(b[np*2][0]), "=r"(b[np*2][1]), "=r"(b[np*2+1][0]), "=r"(b[np*2+1][1])
                         : "r"(addr));
        }
        #pragma unroll
        for (int mi = 0; mi < 4; mi++)
            #pragma unroll
            for (int ni = 0; ni < 4; ni++)
                asm volatile(
                    "mma.sync.aligned.m16n8k16.row.col.f32.bf16.bf16.f32 "
                    "{%0,%1,%2,%3}, {%4,%5,%6,%7}, {%8,%9}, {%0,%1,%2,%3};"
                    : "+f"(acc[mi][ni][0]), "+f"(acc[mi][ni][1]),
                      "+f"(acc[mi][ni][2]), "+f"(acc[mi][ni][3])
                    : "r"(a[mi][0]), "r"(a[mi][1]), "r"(a[mi][2]), "r"(a[mi][3]),
                      "r"(b[ni][0]), "r"(b[ni][1]));
    }

    int g0 = lane >> 2, q4 = lane & 3;
    #pragma unroll
    for (int mi = 0; mi < 4; mi++) {
        int row0 = rowBase + warp_m * 64 + mi * 16 + g0;
        int row1 = row0 + 8;
        #pragma unroll
        for (int ni = 0; ni < 4; ni++) {
            int c0 = colBase + warp_n * 32 + ni * 8 + q4 * 2;
            #pragma unroll
            for (int r = 0; r < 4; r++) {
                int row = (r < 2) ? row0 : row1;
                int col = c0 + (r & 1);
                float v = acc[mi][ni][r];
                if (v * v >= THRESH && row != col) {
                    atomicAdd(&g_cnt[row], 1);
                    if (!diag) atomicAdd(&g_cnt[col], 1);
                }
            }
        }
    }
}

// ---------------------------------------------------------------------------
// Prep: split-bf16 feats, vectorized (bf162). 2 rows per CTA. [hi|hi|lo]
// (proven R13)
// ---------------------------------------------------------------------------
__global__ void prep_feats_kernel(const float* __restrict__ x,
                                  const float* __restrict__ q) {
    int t = threadIdx.x;
    int row = blockIdx.x * 2 + (t >> 7);
    int k2 = t & 127;
    int k = k2 * 2;
    float f0 = 0.0f, f1 = 0.0f;
    if (k < F_DIM) {
        float2 v = *(const float2*)(x + (size_t)row * F_DIM + k);
        f0 = v.x; f1 = v.y;
    } else if (k < F_DIM + Q_DIM) {
        float2 v = *(const float2*)(q + (size_t)row * Q_DIM + (k - F_DIM));
        f0 = v.x; f1 = v.y;
    } else if (k == IN_DIM - 1) {
        f0 = (float)g_cnt[row] * (1.0f / (float)B_ROWS);
    }
    __nv_bfloat16 h0 = __float2bfloat16_rn(f0), h1 = __float2bfloat16_rn(f1);
    __nv_bfloat162 hi(h0, h1);
    __nv_bfloat162 lo(__float2bfloat16_rn(f0 - __bfloat162float(h0)),
                      __float2bfloat16_rn(f1 - __bfloat162float(h1)));
    __nv_bfloat162* base = (__nv_bfloat162*)(g_fpp + (size_t)row * KT);
    base[k2]       = hi;
    base[128 + k2] = hi;
    base[256 + k2] = lo;
}

__global__ void prep_w_kernel(const float* __restrict__ W1,
                              const float* __restrict__ W2) {
    int n = blockIdx.x;
    int k = threadIdx.x;
    {
        float f = (k < IN_DIM) ? W1[(size_t)n * IN_DIM + k] : 0.0f;
        __nv_bfloat16 hi = __float2bfloat16_rn(f);
        __nv_bfloat16 lo = __float2bfloat16_rn(f - __bfloat162float(hi));
        size_t base = (size_t)n * KT;
        g_w1pp[base + k]       = hi;
        g_w1pp[base + 256 + k] = lo;
        g_w1pp[base + 512 + k] = hi;
    }
    {
        float f = W2[(size_t)n * H1D + k];
        __nv_bfloat16 hi = __float2bfloat16_rn(f);
        __nv_bfloat16 lo = __float2bfloat16_rn(f - __bfloat162float(hi));
        size_t base = (size_t)n * KT;
        g_w2pp[base + k]       = hi;
        g_w2pp[base + 256 + k] = lo;
        g_w2pp[base + 512 + k] = hi;
    }
}

// ---------------------------------------------------------------------------
// MLP GEMM (HMMA): K=768 in 6 chunks. MODE 0 -> split h; MODE 1 -> fused
// layer3 partials, one slot per (row, col-tile, warp_n). (proven R13)
// ---------------------------------------------------------------------------
#define MLP_SMEM_DYN 65536

template <int MODE>
__global__ void __launch_bounds__(256) mlp_mma_kernel(const float* __restrict__ bias,
                                                      const float* __restrict__ W3) {
    const __nv_bfloat16* A = (MODE == 0) ? g_fpp  : g_hpp;
    const __nv_bfloat16* W = (MODE == 0) ? g_w1pp : g_w2pp;

    extern __shared__ char smem[];
    int t = threadIdx.x, wid = t >> 5, lane = t & 31;
    int warp_m = wid >> 2, warp_n = wid & 3;
    int mBase = blockIdx.y * 128;
    int nBase = blockIdx.x * 128;

    uint32_t sA = smem_u32(smem);
    uint32_t sB = sA + 32768;

    int a_row_l   = warp_m * 64 + (lane & 15);
    int a_chunk_l = lane >> 4;
    int b_row_l   = warp_n * 32 + ((lane >> 4) << 3) + (lane & 7);
    int b_chunk_l = (lane >> 3) & 1;

    float acc[4][4][4];
    #pragma unroll
    for (int mi = 0; mi < 4; mi++)
        #pragma unroll
        for (int ni = 0; ni < 4; ni++)
            #pragma unroll
            for (int r = 0; r < 4; r++) acc[mi][ni][r] = 0.0f;

    for (int c = 0; c < KT / 128; c++) {
        if (c) __syncthreads();
        #pragma unroll
        for (int l = 0; l < 8; l++) {
            int u = t + l * 256;
            int row = u >> 4, seg = u & 15;
            const char* pa = (const char*)A + (size_t)(mBase + row) * (KT * 2) + c * 256 + seg * 16;
            const char* pw = (const char*)W + (size_t)(nBase + row) * (KT * 2) + c * 256 + seg * 16;
            uint32_t off = SWZ256((uint32_t)row * 256 + seg * 16);
            *(uint4*)(smem + off)         = *(const uint4*)pa;
            *(uint4*)(smem + 32768 + off) = *(const uint4*)pw;
        }
        __syncthreads();

        #pragma unroll
        for (int kk = 0; kk < 8; kk++) {
            uint32_t a[4][4];
            #pragma unroll
            for (int mi = 0; mi < 4; mi++) {
                uint32_t byte = (uint32_t)(a_row_l + mi * 16) * 256 + (kk * 2 + a_chunk_l) * 16;
                uint32_t addr = sA + SWZ256(byte);
                asm volatile("ldmatrix.sync.aligned.m8n8.x4.shared.b16 {%0,%1,%2,%3}, [%4];"
                             : "=r"(a[mi][0]), "=r"(a[mi][1]), "=r"(a[mi][2]), "=r"(a[mi][3])
                             : "r"(addr));
            }
            uint32_t b[4][2];
            #pragma unroll
            for (int np = 0; np < 2; np++) {
                uint32_t byte = (uint32_t)(b_row_l + np * 16) * 256 + (kk * 2 + b_chunk_l) * 16;
                uint32_t addr = sB + SWZ256(byte);
                asm volatile("ldmatrix.sync.aligned.m8n8.x4.shared.b16 {%0,%1,%2,%3}, [%4];"
                             : "=r"(b[np*2][0]), "=r"(b[np*2][1]), "=r"(b[np*2+1][0]), "=r"(b[np*2+1][1])
                             : "r"(addr));
            }
            #pragma unroll
            for (int mi = 0; mi < 4; mi++)
                #pragma unroll
                for (int ni = 0; ni < 4; ni++)
                    asm volatile(
                        "mma.sync.aligned.m16n8k16.row.col.f32.bf16.bf16.f32 "
                        "{%0,%1,%2,%3}, {%4,%5,%6,%7}, {%8,%9}, {%0,%1,%2,%3};"
                        : "+f"(acc[mi][ni][0]), "+f"(acc[mi][ni][1]),
                          "+f"(acc[mi][ni][2]), "+f"(acc[mi][ni][3])
                        : "r"(a[mi][0]), "r"(a[mi][1]), "r"(a[mi][2]), "r"(a[mi][3]),
                          "r"(b[ni][0]), "r"(b[ni][1]));
        }
    }

    int g0 = lane >> 2, q4 = lane & 3;
    #pragma unroll
    for (int mi = 0; mi < 4; mi++) {
        int row0 = mBase + warp_m * 64 + mi * 16 + g0;
        int row1 = row0 + 8;
        float s0 = 0.0f, s1 = 0.0f;
        #pragma unroll
        for (int ni = 0; ni < 4; ni++) {
            int col = nBase + warp_n * 32 + ni * 8 + q4 * 2;
            float bv0 = bias[col], bv1 = bias[col + 1];
            float h00 = fmaxf(acc[mi][ni][0] + bv0, 0.0f);
            float h01 = fmaxf(acc[mi][ni][1] + bv1, 0.0f);
            float h10 = fmaxf(acc[mi][ni][2] + bv0, 0.0f);
            float h11 = fmaxf(acc[mi][ni][3] + bv1, 0.0f);
            if (MODE == 0) {
                __nv_bfloat16 a0 = __float2bfloat16_rn(h00), a1 = __float2bfloat16_rn(h01);
                __nv_bfloat16 c0 = __float2bfloat16_rn(h10), c1 = __float2bfloat16_rn(h11);
                __nv_bfloat162 hi0(a0, a1), hi1(c0, c1);
                __nv_bfloat162 lo0(__float2bfloat16_rn(h00 - __bfloat162float(a0)),
                                   __float2bfloat16_rn(h01 - __bfloat162float(a1)));
                __nv_bfloat162 lo1(__float2bfloat16_rn(h10 - __bfloat162float(c0)),
                                   __float2bfloat16_rn(h11 - __bfloat162float(c1)));
                __nv_bfloat162* p0 = (__nv_bfloat162*)(g_hpp + (size_t)row0 * KT + col);
                __nv_bfloat162* p1 = (__nv_bfloat162*)(g_hpp + (size_t)row1 * KT + col);
                p0[0] = hi0; p0[128] = hi0; p0[256] = lo0;
                p1[0] = hi1; p1[128] = hi1; p1[256] = lo1;
            } else {
                float w0 = W3[col], w1 = W3[col + 1];
                s0 = fmaf(h00, w0, fmaf(h01, w1, s0));
                s1 = fmaf(h10, w0, fmaf(h11, w1, s1));
            }
        }
        if (MODE == 1) {
            s0 += __shfl_xor_sync(0xffffffffu, s0, 1);
            s0 += __shfl_xor_sync(0xffffffffu, s0, 2);
            s1 += __shfl_xor_sync(0xffffffffu, s1, 1);
            s1 += __shfl_xor_sync(0xffffffffu, s1, 2);
            if (q4 == 0) {
                int slot = blockIdx.x * 4 + warp_n;          // 8 slots per row
                g_part[(size_t)row0 * 8 + slot] = s0;
                g_part[(size_t)row1 * 8 + slot] = s1;
            }
        }
    }
}

// ---------------------------------------------------------------------------
// Finalize: out[row] = sum of 8 partials + b3 (deterministic fold). (proven R13)
// ---------------------------------------------------------------------------
__global__ void finalize_kernel(const float* __restrict__ b3,
                                float* __restrict__ out) {
    int i = blockIdx.x * 256 + threadIdx.x;
    const float4* p = (const float4*)(g_part + (size_t)i * 8);
    float4 u = p[0], v = p[1];
    out[i] = ((u.x + u.y) + (u.z + u.w)) + ((v.x + v.y) + (v.z + v.w)) + b3[0];
}

// ---------------------------------------------------------------------------
extern "C" void kernel_launch(void* const* d_in, const int* in_sizes, int n_in,
                              void* d_out, int out_size) {
    const float* x  = (const float*)d_in[0];
    const float* q  = (const float*)d_in[1];
    const float* W1 = (const float*)d_in[2];
    const float* b1 = (const float*)d_in[3];
    const float* W2 = (const float*)d_in[4];
    const float* b2 = (const float*)d_in[5];
    const float* W3 = (const float*)d_in[6];
    const float* b3 = (const float*)d_in[7];
    float* out = (float*)d_out;

    cudaFuncSetAttribute(gram_mma_kernel,
                         cudaFuncAttributeMaxDynamicSharedMemorySize, GRAM_SMEM_DYN);
    cudaFuncSetAttribute(mlp_mma_kernel<0>,
                         cudaFuncAttributeMaxDynamicSharedMemorySize, MLP_SMEM_DYN);
    cudaFuncSetAttribute(mlp_mma_kernel<1>,
                         cudaFuncAttributeMaxDynamicSharedMemorySize, MLP_SMEM_DYN);

    rownorm_kernel<<<B_ROWS / 8, 256>>>(x);
    prep_w_kernel<<<256, 256>>>(W1, W2);
    gram_mma_kernel<<<dim3(B_ROWS / 128, B_ROWS / 128), 256, GRAM_SMEM_DYN>>>();
    prep_feats_kernel<<<B_ROWS / 2, 256>>>(x, q);
    mlp_mma_kernel<0><<<dim3(H1D / 128, B_ROWS / 128), 256, MLP_SMEM_DYN>>>(b1, W3);
    mlp_mma_kernel<1><<<dim3(H2D / 128, B_ROWS / 128), 256, MLP_SMEM_DYN>>>(b2, W3);
    finalize_kernel<<<B_ROWS / 256, 256>>>(b3, out);
}

// round 15
// speedup vs baseline: 1.3632x; 1.1459x over previous
#include <cuda_runtime.h>
#include <cuda_bf16.h>
#include <cstdint>

#define B_ROWS 8192
#define F_DIM 128
#define Q_DIM 64
#define IN_DIM 193
#define H1D 256
#define H2D 256
#define THRESH 0.95f
#define EPSV 1e-12f

#define KT  768   // logical K: [hi|hi|lo] x [wh|wl|wh]
#define KTA 512   // stored A-side cols: [hi|lo] (hi segment deduped)

// Scratch (no allocations allowed)
__device__ __align__(16) __nv_bfloat16 g_xnb[B_ROWS * F_DIM]; // normalized rows, bf16
__device__ int   g_cnt[B_ROWS];
__device__ __align__(16) __nv_bfloat16 g_fpp[B_ROWS * KTA];  // [fh|fl]
__device__ __align__(16) __nv_bfloat16 g_w1pp[H1D * KT];     // [wh|wl|wh]
__device__ __align__(16) __nv_bfloat16 g_hpp[B_ROWS * KTA];  // [hh|hl]
__device__ __align__(16) __nv_bfloat16 g_w2pp[H2D * KT];     // [wh|wl|wh]
__device__ float g_part[B_ROWS * 8];                          // layer3 partials

__device__ __forceinline__ uint32_t smem_u32(const void* p) {
    uint32_t a;
    asm("{ .reg .u64 t; cvta.to.shared.u64 t, %1; cvt.u32.u64 %0, t; }" : "=r"(a) : "l"(p));
    return a;
}
__device__ __forceinline__ void cp_async16(uint32_t dst, const void* src) {
    asm volatile("cp.async.cg.shared.global [%0], [%1], 16;" :: "r"(dst), "l"(src));
}
#define SWZ256(b) ((b) ^ ((((b) >> 8) & 7) << 4))

// ---------------------------------------------------------------------------
// Kernel 1: row L2 norm -> bf16 normalized rows; zero counters (proven)
// ---------------------------------------------------------------------------
__global__ void rownorm_kernel(const float* __restrict__ x) {
    int row  = blockIdx.x * 8 + (threadIdx.x >> 5);
    int lane = threadIdx.x & 31;
    const float4* xr = (const float4*)(x + (size_t)row * F_DIM);
    float4 v = xr[lane];
    float s = v.x * v.x + v.y * v.y + v.z * v.z + v.w * v.w;
    #pragma unroll
    for (int o = 16; o > 0; o >>= 1) s += __shfl_xor_sync(0xffffffffu, s, o);
    float inv = 1.0f / (sqrtf(s) + EPSV);
    __nv_bfloat162* outp = (__nv_bfloat162*)(g_xnb + (size_t)row * F_DIM);
    outp[lane * 2 + 0] = __nv_bfloat162(__float2bfloat16_rn(v.x * inv), __float2bfloat16_rn(v.y * inv));
    outp[lane * 2 + 1] = __nv_bfloat162(__float2bfloat16_rn(v.z * inv), __float2bfloat16_rn(v.w * inv));
    if (lane == 0) g_cnt[row] = 0;
}

// ---------------------------------------------------------------------------
// Kernel 2: symmetric gram-count, bf16 HMMA, linear triangular grid (2080 CTAs).
// ---------------------------------------------------------------------------
#define GRAM_SMEM_DYN 65536

__global__ void __launch_bounds__(256) gram_mma_kernel() {
    // decode upper-triangle (bi, bj) from linear block id
    int bid = blockIdx.x;
    int bi = 0, rem = bid;
    while (rem >= 64 - bi) { rem -= 64 - bi; bi++; }
    int bj = bi + rem;
    const bool diag = (bi == bj);

    extern __shared__ char smem[];
    int t = threadIdx.x, wid = t >> 5, lane = t & 31;
    int warp_m = wid >> 2, warp_n = wid & 3;
    int rowBase = bi * 128;
    int colBase = bj * 128;

    uint32_t sA = smem_u32(smem);
    uint32_t sB = sA + 32768;

    #pragma unroll
    for (int l = 0; l < 8; l++) {
        int u = t + l * 256;
        int row = u >> 4, seg = u & 15;
        uint4 va = ((const uint4*)(g_xnb + (size_t)(rowBase + row) * F_DIM))[seg];
        uint4 vb = ((const uint4*)(g_xnb + (size_t)(colBase + row) * F_DIM))[seg];
        uint32_t off = SWZ256((uint32_t)row * 256 + seg * 16);
        *(uint4*)(smem + off)         = va;
        *(uint4*)(smem + 32768 + off) = vb;
    }
    __syncthreads();

    int a_row_l   = warp_m * 64 + (lane & 15);
    int a_chunk_l = lane >> 4;
    int b_row_l   = warp_n * 32 + ((lane >> 4) << 3) + (lane & 7);
    int b_chunk_l = (lane >> 3) & 1;

    float acc[4][4][4];
    #pragma unroll
    for (int mi = 0; mi < 4; mi++)
        #pragma unroll
        for (int ni = 0; ni < 4; ni++)
            #pragma unroll
            for (int r = 0; r < 4; r++) acc[mi][ni][r] = 0.0f;

    #pragma unroll
    for (int kk = 0; kk < 8; kk++) {
        uint32_t a[4][4];
        #pragma unroll
        for (int mi = 0; mi < 4; mi++) {
            uint32_t byte = (uint32_t)(a_row_l + mi * 16) * 256 + (kk * 2 + a_chunk_l) * 16;
            uint32_t addr = sA + SWZ256(byte);
            asm volatile("ldmatrix.sync.aligned.m8n8.x4.shared.b16 {%0,%1,%2,%3}, [%4];"
                         : "=r"(a[mi][0]), "=r"(a[mi][1]), "=r"(a[mi][2]), "=r"(a[mi][3])
                         : "r"(addr));
        }
        uint32_t b[4][2];
        #pragma unroll
        for (int np = 0; np < 2; np++) {
            uint32_t byte = (uint32_t)(b_row_l + np * 16) * 256 + (kk * 2 + b_chunk_l) * 16;
            uint32_t addr = sB + SWZ256(byte);
            asm volatile("ldmatrix.sync.aligned.m8n8.x4.shared.b16 {%0,%1,%2,%3}, [%4];"
                         : "=r"(b[np*2][0]), "=r"(b[np*2][1]), "=r"(b[np*2+1][0]), "=r"(b[np*2+1][1])
                         : "r"(addr));
        }
        #pragma unroll
        for (int mi = 0; mi < 4; mi++)
            #pragma unroll
            for (int ni = 0; ni < 4; ni++)
                asm volatile(
                    "mma.sync.aligned.m16n8k16.row.col.f32.bf16.bf16.f32 "
                    "{%0,%1,%2,%3}, {%4,%5,%6,%7}, {%8,%9}, {%0,%1,%2,%3};"
                    : "+f"(acc[mi][ni][0]), "+f"(acc[mi][ni][1]),
                      "+f"(acc[mi][ni][2]), "+f"(acc[mi][ni][3])
                    : "r"(a[mi][0]), "r"(a[mi][1]), "r"(a[mi][2]), "r"(a[mi][3]),
                      "r"(b[ni][0]), "r"(b[ni][1]));
    }

    int g0 = lane >> 2, q4 = lane & 3;
    #pragma unroll
    for (int mi = 0; mi < 4; mi++) {
        int row0 = rowBase + warp_m * 64 + mi * 16 + g0;
        int row1 = row0 + 8;
        #pragma unroll
        for (int ni = 0; ni < 4; ni++) {
            int c0 = colBase + warp_n * 32 + ni * 8 + q4 * 2;
            #pragma unroll
            for (int r = 0; r < 4; r++) {
                int row = (r < 2) ? row0 : row1;
                int col = c0 + (r & 1);
                float v = acc[mi][ni][r];
                if (v * v >= THRESH && row != col) {
                    atomicAdd(&g_cnt[row], 1);
                    if (!diag) atomicAdd(&g_cnt[col], 1);
                }
            }
        }
    }
}

// ---------------------------------------------------------------------------
// Prep: split-bf16 feats [fh|fl] (512 cols, hi deduped). 2 rows per CTA.
// ---------------------------------------------------------------------------
__global__ void prep_feats_kernel(const float* __restrict__ x,
                                  const float* __restrict__ q) {
    int t = threadIdx.x;
    int row = blockIdx.x * 2 + (t >> 7);
    int k2 = t & 127;
    int k = k2 * 2;
    float f0 = 0.0f, f1 = 0.0f;
    if (k < F_DIM) {
        float2 v = *(const float2*)(x + (size_t)row * F_DIM + k);
        f0 = v.x; f1 = v.y;
    } else if (k < F_DIM + Q_DIM) {
        float2 v = *(const float2*)(q + (size_t)row * Q_DIM + (k - F_DIM));
        f0 = v.x; f1 = v.y;
    } else if (k == IN_DIM - 1) {
        f0 = (float)g_cnt[row] * (1.0f / (float)B_ROWS);
    }
    __nv_bfloat16 h0 = __float2bfloat16_rn(f0), h1 = __float2bfloat16_rn(f1);
    __nv_bfloat162 hi(h0, h1);
    __nv_bfloat162 lo(__float2bfloat16_rn(f0 - __bfloat162float(h0)),
                      __float2bfloat16_rn(f1 - __bfloat162float(h1)));
    __nv_bfloat162* base = (__nv_bfloat162*)(g_fpp + (size_t)row * KTA);
    base[k2]       = hi;
    base[128 + k2] = lo;
}

__global__ void prep_w_kernel(const float* __restrict__ W1,
                              const float* __restrict__ W2) {
    int n = blockIdx.x;
    int k = threadIdx.x;
    {
        float f = (k < IN_DIM) ? W1[(size_t)n * IN_DIM + k] : 0.0f;
        __nv_bfloat16 hi = __float2bfloat16_rn(f);
        __nv_bfloat16 lo = __float2bfloat16_rn(f - __bfloat162float(hi));
        size_t base = (size_t)n * KT;
        g_w1pp[base + k]       = hi;
        g_w1pp[base + 256 + k] = lo;
        g_w1pp[base + 512 + k] = hi;
    }
    {
        float f = W2[(size_t)n * H1D + k];
        __nv_bfloat16 hi = __float2bfloat16_rn(f);
        __nv_bfloat16 lo = __float2bfloat16_rn(f - __bfloat162float(hi));
        size_t base = (size_t)n * KT;
        g_w2pp[base + k]       = hi;
        g_w2pp[base + 256 + k] = lo;
        g_w2pp[base + 512 + k] = hi;
    }
}

// ---------------------------------------------------------------------------
// MLP GEMM (HMMA), cp.async 2-stage pipeline, K=768 in 6 chunks of 128 cols.
// A stored deduped (512 cols): chunk remap c -> (c<2 ? c : c-2).
// MODE 0 -> split h [hh|hl]; MODE 1 -> fused layer3 partials (8 slots/row).
// ---------------------------------------------------------------------------
#define MLP_SMEM_DYN 131072

template <int MODE>
__global__ void __launch_bounds__(256) mlp_mma_kernel(const float* __restrict__ bias,
                                                      const float* __restrict__ W3) {
    const __nv_bfloat16* A = (MODE == 0) ? g_fpp  : g_hpp;
    const __nv_bfloat16* W = (MODE == 0) ? g_w1pp : g_w2pp;
    const int NC = KT / 128;

    extern __shared__ char smem[];
    int t = threadIdx.x, wid = t >> 5, lane = t & 31;
    int warp_m = wid >> 2, warp_n = wid & 3;
    int mBase = blockIdx.y * 128;
    int nBase = blockIdx.x * 128;
    uint32_t sbase = smem_u32(smem);

    // Issue cp.async for one chunk into one stage (A: deduped source chunk).
    auto load_chunk = [&](int c, int stage) {
        int ca = (c < 2) ? c : (c - 2);          // A chunk in [fh|fl] storage
        uint32_t dA = sbase + stage * 65536;
        uint32_t dW = dA + 32768;
        #pragma unroll
        for (int l = 0; l < 8; l++) {
            int u = t + l * 256;
            int row = u >> 4, seg = u & 15;
            uint32_t off = SWZ256((uint32_t)row * 256 + seg * 16);
            const char* pa = (const char*)A + (size_t)(mBase + row) * (KTA * 2) + ca * 256 + seg * 16;
            const char* pw = (const char*)W + (size_t)(nBase + row) * (KT * 2)  + c  * 256 + seg * 16;
            cp_async16(dA + off, pa);
            cp_async16(dW + off, pw);
        }
        asm volatile("cp.async.commit_group;" ::: "memory");
    };

    int a_row_l   = warp_m * 64 + (lane & 15);
    int a_chunk_l = lane >> 4;
    int b_row_l   = warp_n * 32 + ((lane >> 4) << 3) + (lane & 7);
    int b_chunk_l = (lane >> 3) & 1;

    float acc[4][4][4];
    #pragma unroll
    for (int mi = 0; mi < 4; mi++)
        #pragma unroll
        for (int ni = 0; ni < 4; ni++)
            #pragma unroll
            for (int r = 0; r < 4; r++) acc[mi][ni][r] = 0.0f;

    load_chunk(0, 0);
    for (int c = 0; c < NC; c++) {
        if (c + 1 < NC) {
            load_chunk(c + 1, (c + 1) & 1);
            asm volatile("cp.async.wait_group 1;" ::: "memory");
        } else {
            asm volatile("cp.async.wait_group 0;" ::: "memory");
        }
        __syncthreads();                         // chunk c visible to all threads

        uint32_t sA = sbase + (uint32_t)(c & 1) * 65536;
        uint32_t sB = sA + 32768;
        #pragma unroll
        for (int kk = 0; kk < 8; kk++) {
            uint32_t a[4][4];
            #pragma unroll
            for (int mi = 0; mi < 4; mi++) {
                uint32_t byte = (uint32_t)(a_row_l + mi * 16) * 256 + (kk * 2 + a_chunk_l) * 16;
                uint32_t addr = sA + SWZ256(byte);
                asm volatile("ldmatrix.sync.aligned.m8n8.x4.shared.b16 {%0,%1,%2,%3}, [%4];"
                             : "=r"(a[mi][0]), "=r"(a[mi][1]), "=r"(a[mi][2]), "=r"(a[mi][3])
                             : "r"(addr));
            }
            uint32_t b[4][2];
            #pragma unroll
            for (int np = 0; np < 2; np++) {
                uint32_t byte = (uint32_t)(b_row_l + np * 16) * 256 + (kk * 2 + b_chunk_l) * 16;
                uint32_t addr = sB + SWZ256(byte);
                asm volatile("ldmatrix.sync.aligned.m8n8.x4.shared.b16 {%0,%1,%2,%3}, [%4];"
                             : "=r"(b[np*2][0]), "=r"(b[np*2][1]), "=r"(b[np*2+1][0]), "=r"(b[np*2+1][1])
                             : "r"(addr));
            }
            #pragma unroll
            for (int mi = 0; mi < 4; mi++)
                #pragma unroll
                for (int ni = 0; ni < 4; ni++)
                    asm volatile(
                        "mma.sync.aligned.m16n8k16.row.col.f32.bf16.bf16.f32 "
                        "{%0,%1,%2,%3}, {%4,%5,%6,%7}, {%8,%9}, {%0,%1,%2,%3};"
                        : "+f"(acc[mi][ni][0]), "+f"(acc[mi][ni][1]),
                          "+f"(acc[mi][ni][2]), "+f"(acc[mi][ni][3])
                        : "r"(a[mi][0]), "r"(a[mi][1]), "r"(a[mi][2]), "r"(a[mi][3]),
                          "r"(b[ni][0]), "r"(b[ni][1]));
        }
        __syncthreads();                         // done reading before overwrite
    }

    int g0 = lane >> 2, q4 = lane & 3;
    #pragma unroll
    for (int mi = 0; mi < 4; mi++) {
        int row0 = mBase + warp_m * 64 + mi * 16 + g0;
        int row1 = row0 + 8;
        float s0 = 0.0f, s1 = 0.0f;
        #pragma unroll
        for (int ni = 0; ni < 4; ni++) {
            int col = nBase + warp_n * 32 + ni * 8 + q4 * 2;
            float bv0 = bias[col], bv1 = bias[col + 1];
            float h00 = fmaxf(acc[mi][ni][0] + bv0, 0.0f);
            float h01 = fmaxf(acc[mi][ni][1] + bv1, 0.0f);
            float h10 = fmaxf(acc[mi][ni][2] + bv0, 0.0f);
            float h11 = fmaxf(acc[mi][ni][3] + bv1, 0.0f);
            if (MODE == 0) {
                __nv_bfloat16 a0 = __float2bfloat16_rn(h00), a1 = __float2bfloat16_rn(h01);
                __nv_bfloat16 c0 = __float2bfloat16_rn(h10), c1 = __float2bfloat16_rn(h11);
                __nv_bfloat162 hi0(a0, a1), hi1(c0, c1);
                __nv_bfloat162 lo0(__float2bfloat16_rn(h00 - __bfloat162float(a0)),
                                   __float2bfloat16_rn(h01 - __bfloat162float(a1)));
                __nv_bfloat162 lo1(__float2bfloat16_rn(h10 - __bfloat162float(c0)),
                                   __float2bfloat16_rn(h11 - __bfloat162float(c1)));
                __nv_bfloat162* p0 = (__nv_bfloat162*)(g_hpp + (size_t)row0 * KTA + col);
                __nv_bfloat162* p1 = (__nv_bfloat162*)(g_hpp + (size_t)row1 * KTA + col);
                p0[0] = hi0; p0[128] = lo0;      // cols +0 / +256 in [hh|hl]
                p1[0] = hi1; p1[128] = lo1;
            } else {
                float w0 = W3[col], w1 = W3[col + 1];
                s0 = fmaf(h00, w0, fmaf(h01, w1, s0));
                s1 = fmaf(h10, w0, fmaf(h11, w1, s1));
            }
        }
        if (MODE == 1) {
            s0 += __shfl_xor_sync(0xffffffffu, s0, 1);
            s0 += __shfl_xor_sync(0xffffffffu, s0, 2);
            s1 += __shfl_xor_sync(0xffffffffu, s1, 1);
            s1 += __shfl_xor_sync(0xffffffffu, s1, 2);
            if (q4 == 0) {
                int slot = blockIdx.x * 4 + warp_n;
                g_part[(size_t)row0 * 8 + slot] = s0;
                g_part[(size_t)row1 * 8 + slot] = s1;
            }
        }
    }
}

// ---------------------------------------------------------------------------
// Finalize: out[row] = sum of 8 partials + b3.
// ---------------------------------------------------------------------------
__global__ void finalize_kernel(const float* __restrict__ b3,
                                float* __restrict__ out) {
    int i = blockIdx.x * 256 + threadIdx.x;
    const float4* p = (const float4*)(g_part + (size_t)i * 8);
    float4 u = p[0], v = p[1];
    out[i] = ((u.x + u.y) + (u.z + u.w)) + ((v.x + v.y) + (v.z + v.w)) + b3[0];
}

// ---------------------------------------------------------------------------
extern "C" void kernel_launch(void* const* d_in, const int* in_sizes, int n_in,
                              void* d_out, int out_size) {
    const float* x  = (const float*)d_in[0];
    const float* q  = (const float*)d_in[1];
    const float* W1 = (const float*)d_in[2];
    const float* b1 = (const float*)d_in[3];
    const float* W2 = (const float*)d_in[4];
    const float* b2 = (const float*)d_in[5];
    const float* W3 = (const float*)d_in[6];
    const float* b3 = (const float*)d_in[7];
    float* out = (float*)d_out;

    cudaFuncSetAttribute(gram_mma_kernel,
                         cudaFuncAttributeMaxDynamicSharedMemorySize, GRAM_SMEM_DYN);
    cudaFuncSetAttribute(mlp_mma_kernel<0>,
                         cudaFuncAttributeMaxDynamicSharedMemorySize, MLP_SMEM_DYN);
    cudaFuncSetAttribute(mlp_mma_kernel<1>,
                         cudaFuncAttributeMaxDynamicSharedMemorySize, MLP_SMEM_DYN);

    rownorm_kernel<<<B_ROWS / 8, 256>>>(x);
    prep_w_kernel<<<256, 256>>>(W1, W2);
    gram_mma_kernel<<<2080, 256, GRAM_SMEM_DYN>>>();
    prep_feats_kernel<<<B_ROWS / 2, 256>>>(x, q);
    mlp_mma_kernel<0><<<dim3(H1D / 128, B_ROWS / 128), 256, MLP_SMEM_DYN>>>(b1, W3);
    mlp_mma_kernel<1><<<dim3(H2D / 128, B_ROWS / 128), 256, MLP_SMEM_DYN>>>(b2, W3);
    finalize_kernel<<<B_ROWS / 256, 256>>>(b3, out);
}

// round 16
// speedup vs baseline: 1.4358x; 1.0532x over previous
#include <cuda_runtime.h>
#include <cuda_bf16.h>
#include <cstdint>

#define B_ROWS 8192
#define F_DIM 128
#define Q_DIM 64
#define IN_DIM 193
#define H1D 256
#define H2D 256
#define THRESH 0.95f
#define EPSV 1e-12f

#define KT  768   // logical K: [hi|hi|lo] x [wh|wl|wh]
#define KTA 512   // stored A-side cols: [hi|lo]

// Scratch (no allocations allowed)
__device__ __align__(16) __nv_bfloat16 g_xnb[B_ROWS * F_DIM];
__device__ int   g_cnt[B_ROWS];
__device__ __align__(16) __nv_bfloat16 g_fpp[B_ROWS * KTA];  // [fh|fl]
__device__ __align__(16) __nv_bfloat16 g_w1pp[H1D * KT];     // [wh|wl|wh]
__device__ __align__(16) __nv_bfloat16 g_hpp[B_ROWS * KTA];  // [hh|hl]
__device__ __align__(16) __nv_bfloat16 g_w2pp[H2D * KT];     // [wh|wl|wh]
__device__ float g_part[B_ROWS * 8];

__device__ __forceinline__ uint32_t smem_u32(const void* p) {
    uint32_t a;
    asm("{ .reg .u64 t; cvta.to.shared.u64 t, %1; cvt.u32.u64 %0, t; }" : "=r"(a) : "l"(p));
    return a;
}
__device__ __forceinline__ void cp_async16(uint32_t dst, const void* src) {
    asm volatile("cp.async.cg.shared.global [%0], [%1], 16;" :: "r"(dst), "l"(src));
}
#define SWZ256(b) ((b) ^ ((((b) >> 8) & 7) << 4))

__device__ __forceinline__ __nv_bfloat162 hi2(float a, float b) {
    return __nv_bfloat162(__float2bfloat16_rn(a), __float2bfloat16_rn(b));
}
__device__ __forceinline__ __nv_bfloat162 lo2(float a, float b) {
    __nv_bfloat16 ha = __float2bfloat16_rn(a), hb = __float2bfloat16_rn(b);
    return __nv_bfloat162(__float2bfloat16_rn(a - __bfloat162float(ha)),
                          __float2bfloat16_rn(b - __bfloat162float(hb)));
}

// ---------------------------------------------------------------------------
// Kernel 1: row L2 norm -> bf16 normalized rows; zero counters; ALSO writes
// the gram-independent part of g_fpp (raw x cols 0..127, q cols 128..191,
// zeros 192..255, in both hi and lo segments). One warp per row.
// ---------------------------------------------------------------------------
__global__ void rownorm_kernel(const float* __restrict__ x,
                               const float* __restrict__ q) {
    int row  = blockIdx.x * 8 + (threadIdx.x >> 5);
    int lane = threadIdx.x & 31;
    const float4* xr = (const float4*)(x + (size_t)row * F_DIM);
    float4 v = xr[lane];
    float s = v.x * v.x + v.y * v.y + v.z * v.z + v.w * v.w;
    #pragma unroll
    for (int o = 16; o > 0; o >>= 1) s += __shfl_xor_sync(0xffffffffu, s, o);
    float inv = 1.0f / (sqrtf(s) + EPSV);
    __nv_bfloat162* outp = (__nv_bfloat162*)(g_xnb + (size_t)row * F_DIM);
    outp[lane * 2 + 0] = hi2(v.x * inv, v.y * inv);
    outp[lane * 2 + 1] = hi2(v.z * inv, v.w * inv);
    if (lane == 0) g_cnt[row] = 0;

    // feats split (raw values)
    __nv_bfloat162* base = (__nv_bfloat162*)(g_fpp + (size_t)row * KTA);
    base[lane * 2 + 0]       = hi2(v.x, v.y);
    base[lane * 2 + 1]       = hi2(v.z, v.w);
    base[128 + lane * 2 + 0] = lo2(v.x, v.y);
    base[128 + lane * 2 + 1] = lo2(v.z, v.w);
    if (lane < 16) {
        float4 qv = ((const float4*)(q + (size_t)row * Q_DIM))[lane];
        base[64 + lane * 2 + 0]       = hi2(qv.x, qv.y);
        base[64 + lane * 2 + 1]       = hi2(qv.z, qv.w);
        base[192 + lane * 2 + 0]      = lo2(qv.x, qv.y);
        base[192 + lane * 2 + 1]      = lo2(qv.z, qv.w);
    }
    // zero pad cols 192..255 (k2 96..127 hi, 224..255 lo)
    base[96 + lane]  = __nv_bfloat162(__float2bfloat16_rn(0.0f), __float2bfloat16_rn(0.0f));
    base[224 + lane] = __nv_bfloat162(__float2bfloat16_rn(0.0f), __float2bfloat16_rn(0.0f));
}

// ---------------------------------------------------------------------------
// Kernel 2: symmetric gram-count, bf16 HMMA, triangular grid, cp.async loads.
// ---------------------------------------------------------------------------
#define GRAM_SMEM_DYN 65536

__global__ void __launch_bounds__(256) gram_mma_kernel() {
    int bid = blockIdx.x;
    int bi = 0, rem = bid;
    while (rem >= 64 - bi) { rem -= 64 - bi; bi++; }
    int bj = bi + rem;
    const bool diag = (bi == bj);

    extern __shared__ char smem[];
    int t = threadIdx.x, wid = t >> 5, lane = t & 31;
    int warp_m = wid >> 2, warp_n = wid & 3;
    int rowBase = bi * 128;
    int colBase = bj * 128;

    uint32_t sA = smem_u32(smem);
    uint32_t sB = sA + 32768;

    #pragma unroll
    for (int l = 0; l < 8; l++) {
        int u = t + l * 256;
        int row = u >> 4, seg = u & 15;
        uint32_t off = SWZ256((uint32_t)row * 256 + seg * 16);
        cp_async16(sA + off, (const char*)g_xnb + (size_t)(rowBase + row) * 256 + seg * 16);
        cp_async16(sB + off, (const char*)g_xnb + (size_t)(colBase + row) * 256 + seg * 16);
    }
    asm volatile("cp.async.commit_group;" ::: "memory");
    asm volatile("cp.async.wait_group 0;" ::: "memory");
    __syncthreads();

    int a_row_l   = warp_m * 64 + (lane & 15);
    int a_chunk_l = lane >> 4;
    int b_row_l   = warp_n * 32 + ((lane >> 4) << 3) + (lane & 7);
    int b_chunk_l = (lane >> 3) & 1;

    float acc[4][4][4];
    #pragma unroll
    for (int mi = 0; mi < 4; mi++)
        #pragma unroll
        for (int ni = 0; ni < 4; ni++)
            #pragma unroll
            for (int r = 0; r < 4; r++) acc[mi][ni][r] = 0.0f;

    #pragma unroll
    for (int kk = 0; kk < 8; kk++) {
        uint32_t a[4][4];
        #pragma unroll
        for (int mi = 0; mi < 4; mi++) {
            uint32_t byte = (uint32_t)(a_row_l + mi * 16) * 256 + (kk * 2 + a_chunk_l) * 16;
            uint32_t addr = sA + SWZ256(byte);
            asm volatile("ldmatrix.sync.aligned.m8n8.x4.shared.b16 {%0,%1,%2,%3}, [%4];"
                         : "=r"(a[mi][0]), "=r"(a[mi][1]), "=r"(a[mi][2]), "=r"(a[mi][3])
                         : "r"(addr));
        }
        uint32_t b[4][2];
        #pragma unroll
        for (int np = 0; np < 2; np++) {
            uint32_t byte = (uint32_t)(b_row_l + np * 16) * 256 + (kk * 2 + b_chunk_l) * 16;
            uint32_t addr = sB + SWZ256(byte);
            asm volatile("ldmatrix.sync.aligned.m8n8.x4.shared.b16 {%0,%1,%2,%3}, [%4];"
                         : "=r"(b[np*2][0]), "=r"(b[np*2][1]), "=r"(b[np*2+1][0]), "=r"(b[np*2+1][1])
                         : "r"(addr));
        }
        #pragma unroll
        for (int mi = 0; mi < 4; mi++)
            #pragma unroll
            for (int ni = 0; ni < 4; ni++)
                asm volatile(
                    "mma.sync.aligned.m16n8k16.row.col.f32.bf16.bf16.f32 "
                    "{%0,%1,%2,%3}, {%4,%5,%6,%7}, {%8,%9}, {%0,%1,%2,%3};"
                    : "+f"(acc[mi][ni][0]), "+f"(acc[mi][ni][1]),
                      "+f"(acc[mi][ni][2]), "+f"(acc[mi][ni][3])
                    : "r"(a[mi][0]), "r"(a[mi][1]), "r"(a[mi][2]), "r"(a[mi][3]),
                      "r"(b[ni][0]), "r"(b[ni][1]));
    }

    int g0 = lane >> 2, q4 = lane & 3;
    #pragma unroll
    for (int mi = 0; mi < 4; mi++) {
        int row0 = rowBase + warp_m * 64 + mi * 16 + g0;
        int row1 = row0 + 8;
        #pragma unroll
        for (int ni = 0; ni < 4; ni++) {
            int c0 = colBase + warp_n * 32 + ni * 8 + q4 * 2;
            #pragma unroll
            for (int r = 0; r < 4; r++) {
                int row = (r < 2) ? row0 : row1;
                int col = c0 + (r & 1);
                float v = acc[mi][ni][r];
                if (v * v >= THRESH && row != col) {
                    atomicAdd(&g_cnt[row], 1);
                    if (!diag) atomicAdd(&g_cnt[col], 1);
                }
            }
        }
    }
}

// ---------------------------------------------------------------------------
// Graph-feature column: writes hi/lo of cnt/8192 at col 192 (pad col 193 = 0).
// ---------------------------------------------------------------------------
__global__ void graphcol_kernel() {
    int row = blockIdx.x * 256 + threadIdx.x;
    float g = (float)g_cnt[row] * (1.0f / (float)B_ROWS);
    __nv_bfloat162* base = (__nv_bfloat162*)(g_fpp + (size_t)row * KTA);
    base[96]  = hi2(g, 0.0f);
    base[224] = lo2(g, 0.0f);
}

__global__ void prep_w_kernel(const float* __restrict__ W1,
                              const float* __restrict__ W2) {
    int n = blockIdx.x;
    int k = threadIdx.x;
    {
        float f = (k < IN_DIM) ? W1[(size_t)n * IN_DIM + k] : 0.0f;
        __nv_bfloat16 hi = __float2bfloat16_rn(f);
        __nv_bfloat16 lo = __float2bfloat16_rn(f - __bfloat162float(hi));
        size_t base = (size_t)n * KT;
        g_w1pp[base + k]       = hi;
        g_w1pp[base + 256 + k] = lo;
        g_w1pp[base + 512 + k] = hi;
    }
    {
        float f = W2[(size_t)n * H1D + k];
        __nv_bfloat16 hi = __float2bfloat16_rn(f);
        __nv_bfloat16 lo = __float2bfloat16_rn(f - __bfloat162float(hi));
        size_t base = (size_t)n * KT;
        g_w2pp[base + k]       = hi;
        g_w2pp[base + 256 + k] = lo;
        g_w2pp[base + 512 + k] = hi;
    }
}

// ---------------------------------------------------------------------------
// MLP GEMM (HMMA), cp.async 2-stage pipeline, K=768 in 6 chunks (proven R15).
// ---------------------------------------------------------------------------
#define MLP_SMEM_DYN 131072

template <int MODE>
__global__ void __launch_bounds__(256) mlp_mma_kernel(const float* __restrict__ bias,
                                                      const float* __restrict__ W3) {
    const __nv_bfloat16* A = (MODE == 0) ? g_fpp  : g_hpp;
    const __nv_bfloat16* W = (MODE == 0) ? g_w1pp : g_w2pp;
    const int NC = KT / 128;

    extern __shared__ char smem[];
    int t = threadIdx.x, wid = t >> 5, lane = t & 31;
    int warp_m = wid >> 2, warp_n = wid & 3;
    int mBase = blockIdx.y * 128;
    int nBase = blockIdx.x * 128;
    uint32_t sbase = smem_u32(smem);

    auto load_chunk = [&](int c, int stage) {
        int ca = (c < 2) ? c : (c - 2);
        uint32_t dA = sbase + stage * 65536;
        uint32_t dW = dA + 32768;
        #pragma unroll
        for (int l = 0; l < 8; l++) {
            int u = t + l * 256;
            int row = u >> 4, seg = u & 15;
            uint32_t off = SWZ256((uint32_t)row * 256 + seg * 16);
            const char* pa = (const char*)A + (size_t)(mBase + row) * (KTA * 2) + ca * 256 + seg * 16;
            const char* pw = (const char*)W + (size_t)(nBase + row) * (KT * 2)  + c  * 256 + seg * 16;
            cp_async16(dA + off, pa);
            cp_async16(dW + off, pw);
        }
        asm volatile("cp.async.commit_group;" ::: "memory");
    };

    int a_row_l   = warp_m * 64 + (lane & 15);
    int a_chunk_l = lane >> 4;
    int b_row_l   = warp_n * 32 + ((lane >> 4) << 3) + (lane & 7);
    int b_chunk_l = (lane >> 3) & 1;

    float acc[4][4][4];
    #pragma unroll
    for (int mi = 0; mi < 4; mi++)
        #pragma unroll
        for (int ni = 0; ni < 4; ni++)
            #pragma unroll
            for (int r = 0; r < 4; r++) acc[mi][ni][r] = 0.0f;

    load_chunk(0, 0);
    for (int c = 0; c < NC; c++) {
        if (c + 1 < NC) {
            load_chunk(c + 1, (c + 1) & 1);
            asm volatile("cp.async.wait_group 1;" ::: "memory");
        } else {
            asm volatile("cp.async.wait_group 0;" ::: "memory");
        }
        __syncthreads();

        uint32_t sA = sbase + (uint32_t)(c & 1) * 65536;
        uint32_t sB = sA + 32768;
        #pragma unroll
        for (int kk = 0; kk < 8; kk++) {
            uint32_t a[4][4];
            #pragma unroll
            for (int mi = 0; mi < 4; mi++) {
                uint32_t byte = (uint32_t)(a_row_l + mi * 16) * 256 + (kk * 2 + a_chunk_l) * 16;
                uint32_t addr = sA + SWZ256(byte);
                asm volatile("ldmatrix.sync.aligned.m8n8.x4.shared.b16 {%0,%1,%2,%3}, [%4];"
                             : "=r"(a[mi][0]), "=r"(a[mi][1]), "=r"(a[mi][2]), "=r"(a[mi][3])
                             : "r"(addr));
            }
            uint32_t b[4][2];
            #pragma unroll
            for (int np = 0; np < 2; np++) {
                uint32_t byte = (uint32_t)(b_row_l + np * 16) * 256 + (kk * 2 + b_chunk_l) * 16;
                uint32_t addr = sB + SWZ256(byte);
                asm volatile("ldmatrix.sync.aligned.m8n8.x4.shared.b16 {%0,%1,%2,%3}, [%4];"
                             : "=r"(b[np*2][0]), "=r"(b[np*2][1]), "=r"(b[np*2+1][0]), "=r"(b[np*2+1][1])
                             : "r"(addr));
            }
            #pragma unroll
            for (int mi = 0; mi < 4; mi++)
                #pragma unroll
                for (int ni = 0; ni < 4; ni++)
                    asm volatile(
                        "mma.sync.aligned.m16n8k16.row.col.f32.bf16.bf16.f32 "
                        "{%0,%1,%2,%3}, {%4,%5,%6,%7}, {%8,%9}, {%0,%1,%2,%3};"
                        : "+f"(acc[mi][ni][0]), "+f"(acc[mi][ni][1]),
                          "+f"(acc[mi][ni][2]), "+f"(acc[mi][ni][3])
                        : "r"(a[mi][0]), "r"(a[mi][1]), "r"(a[mi][2]), "r"(a[mi][3]),
                          "r"(b[ni][0]), "r"(b[ni][1]));
        }
        __syncthreads();
    }

    int g0 = lane >> 2, q4 = lane & 3;
    #pragma unroll
    for (int mi = 0; mi < 4; mi++) {
        int row0 = mBase + warp_m * 64 + mi * 16 + g0;
        int row1 = row0 + 8;
        float s0 = 0.0f, s1 = 0.0f;
        #pragma unroll
        for (int ni = 0; ni < 4; ni++) {
            int col = nBase + warp_n * 32 + ni * 8 + q4 * 2;
            float bv0 = bias[col], bv1 = bias[col + 1];
            float h00 = fmaxf(acc[mi][ni][0] + bv0, 0.0f);
            float h01 = fmaxf(acc[mi][ni][1] + bv1, 0.0f);
            float h10 = fmaxf(acc[mi][ni][2] + bv0, 0.0f);
            float h11 = fmaxf(acc[mi][ni][3] + bv1, 0.0f);
            if (MODE == 0) {
                __nv_bfloat162* p0 = (__nv_bfloat162*)(g_hpp + (size_t)row0 * KTA + col);
                __nv_bfloat162* p1 = (__nv_bfloat162*)(g_hpp + (size_t)row1 * KTA + col);
                p0[0] = hi2(h00, h01); p0[128] = lo2(h00, h01);
                p1[0] = hi2(h10, h11); p1[128] = lo2(h10, h11);
            } else {
                float w0 = W3[col], w1 = W3[col + 1];
                s0 = fmaf(h00, w0, fmaf(h01, w1, s0));
                s1 = fmaf(h10, w0, fmaf(h11, w1, s1));
            }
        }
        if (MODE == 1) {
            s0 += __shfl_xor_sync(0xffffffffu, s0, 1);
            s0 += __shfl_xor_sync(0xffffffffu, s0, 2);
            s1 += __shfl_xor_sync(0xffffffffu, s1, 1);
            s1 += __shfl_xor_sync(0xffffffffu, s1, 2);
            if (q4 == 0) {
                int slot = blockIdx.x * 4 + warp_n;
                g_part[(size_t)row0 * 8 + slot] = s0;
                g_part[(size_t)row1 * 8 + slot] = s1;
            }
        }
    }
}

// ---------------------------------------------------------------------------
__global__ void finalize_kernel(const float* __restrict__ b3,
                                float* __restrict__ out) {
    int i = blockIdx.x * 256 + threadIdx.x;
    const float4* p = (const float4*)(g_part + (size_t)i * 8);
    float4 u = p[0], v = p[1];
    out[i] = ((u.x + u.y) + (u.z + u.w)) + ((v.x + v.y) + (v.z + v.w)) + b3[0];
}

// ---------------------------------------------------------------------------
extern "C" void kernel_launch(void* const* d_in, const int* in_sizes, int n_in,
                              void* d_out, int out_size) {
    const float* x  = (const float*)d_in[0];
    const float* q  = (const float*)d_in[1];
    const float* W1 = (const float*)d_in[2];
    const float* b1 = (const float*)d_in[3];
    const float* W2 = (const float*)d_in[4];
    const float* b2 = (const float*)d_in[5];
    const float* W3 = (const float*)d_in[6];
    const float* b3 = (const float*)d_in[7];
    float* out = (float*)d_out;

    cudaFuncSetAttribute(gram_mma_kernel,
                         cudaFuncAttributeMaxDynamicSharedMemorySize, GRAM_SMEM_DYN);
    cudaFuncSetAttribute(mlp_mma_kernel<0>,
                         cudaFuncAttributeMaxDynamicSharedMemorySize, MLP_SMEM_DYN);
    cudaFuncSetAttribute(mlp_mma_kernel<1>,
                         cudaFuncAttributeMaxDynamicSharedMemorySize, MLP_SMEM_DYN);

    rownorm_kernel<<<B_ROWS / 8, 256>>>(x, q);
    prep_w_kernel<<<256, 256>>>(W1, W2);
    gram_mma_kernel<<<2080, 256, GRAM_SMEM_DYN>>>();
    graphcol_kernel<<<B_ROWS / 256, 256>>>();
    mlp_mma_kernel<0><<<dim3(H1D / 128, B_ROWS / 128), 256, MLP_SMEM_DYN>>>(b1, W3);
    mlp_mma_kernel<1><<<dim3(H2D / 128, B_ROWS / 128), 256, MLP_SMEM_DYN>>>(b2, W3);
    finalize_kernel<<<B_ROWS / 256, 256>>>(b3, out);
}

// round 17
// speedup vs baseline: 1.4836x; 1.0333x over previous
#include <cuda_runtime.h>
#include <cuda_bf16.h>
#include <cstdint>

#define B_ROWS 8192
#define F_DIM 128
#define Q_DIM 64
#define IN_DIM 193
#define H1D 256
#define H2D 256
#define THRESH 0.95f
#define EPSV 1e-12f

#define KT  768   // logical K: [hi|hi|lo] x [wh|wl|wh]
#define KTA 512   // stored A-side cols: [hi|lo]

// Scratch (no allocations allowed)
__device__ __align__(16) __nv_bfloat16 g_xnb[B_ROWS * F_DIM];
__device__ int   g_cnt[B_ROWS];
__device__ __align__(16) __nv_bfloat16 g_fpp[B_ROWS * KTA];  // [fh|fl]
__device__ __align__(16) __nv_bfloat16 g_w1pp[H1D * KT];     // [wh|wl|wh]
__device__ __align__(16) __nv_bfloat16 g_hpp[B_ROWS * KTA];  // [hh|hl]
__device__ __align__(16) __nv_bfloat16 g_w2pp[H2D * KT];     // [wh|wl|wh]
__device__ float g_part[B_ROWS * 8];

__device__ __forceinline__ uint32_t smem_u32(const void* p) {
    uint32_t a;
    asm("{ .reg .u64 t; cvta.to.shared.u64 t, %1; cvt.u32.u64 %0, t; }" : "=r"(a) : "l"(p));
    return a;
}
__device__ __forceinline__ void cp_async16(uint32_t dst, const void* src) {
    asm volatile("cp.async.cg.shared.global [%0], [%1], 16;" :: "r"(dst), "l"(src));
}
#define SWZ256(b) ((b) ^ ((((b) >> 8) & 7) << 4))

__device__ __forceinline__ __nv_bfloat162 hi2(float a, float b) {
    return __nv_bfloat162(__float2bfloat16_rn(a), __float2bfloat16_rn(b));
}
__device__ __forceinline__ __nv_bfloat162 lo2(float a, float b) {
    __nv_bfloat16 ha = __float2bfloat16_rn(a), hb = __float2bfloat16_rn(b);
    return __nv_bfloat162(__float2bfloat16_rn(a - __bfloat162float(ha)),
                          __float2bfloat16_rn(b - __bfloat162float(hb)));
}

// ---------------------------------------------------------------------------
// Kernel 1 (fused): blocks 0..1023 = rownorm + feats split; blocks 1024..1279
// = weight split (prep_w).
// ---------------------------------------------------------------------------
__global__ void rownorm_prepw_kernel(const float* __restrict__ x,
                                     const float* __restrict__ q,
                                     const float* __restrict__ W1,
                                     const float* __restrict__ W2) {
    if (blockIdx.x >= B_ROWS / 8) {
        // --- prep_w branch ---
        int n = blockIdx.x - B_ROWS / 8;          // 0..255
        int k = threadIdx.x;                      // 0..255
        {
            float f = (k < IN_DIM) ? W1[(size_t)n * IN_DIM + k] : 0.0f;
            __nv_bfloat16 hi = __float2bfloat16_rn(f);
            __nv_bfloat16 lo = __float2bfloat16_rn(f - __bfloat162float(hi));
            size_t base = (size_t)n * KT;
            g_w1pp[base + k]       = hi;
            g_w1pp[base + 256 + k] = lo;
            g_w1pp[base + 512 + k] = hi;
        }
        {
            float f = W2[(size_t)n * H1D + k];
            __nv_bfloat16 hi = __float2bfloat16_rn(f);
            __nv_bfloat16 lo = __float2bfloat16_rn(f - __bfloat162float(hi));
            size_t base = (size_t)n * KT;
            g_w2pp[base + k]       = hi;
            g_w2pp[base + 256 + k] = lo;
            g_w2pp[base + 512 + k] = hi;
        }
        return;
    }

    // --- rownorm + feats split branch ---
    int row  = blockIdx.x * 8 + (threadIdx.x >> 5);
    int lane = threadIdx.x & 31;
    const float4* xr = (const float4*)(x + (size_t)row * F_DIM);
    float4 v = xr[lane];
    float s = v.x * v.x + v.y * v.y + v.z * v.z + v.w * v.w;
    #pragma unroll
    for (int o = 16; o > 0; o >>= 1) s += __shfl_xor_sync(0xffffffffu, s, o);
    float inv = 1.0f / (sqrtf(s) + EPSV);
    __nv_bfloat162* outp = (__nv_bfloat162*)(g_xnb + (size_t)row * F_DIM);
    outp[lane * 2 + 0] = hi2(v.x * inv, v.y * inv);
    outp[lane * 2 + 1] = hi2(v.z * inv, v.w * inv);
    if (lane == 0) g_cnt[row] = 0;

    __nv_bfloat162* base = (__nv_bfloat162*)(g_fpp + (size_t)row * KTA);
    base[lane * 2 + 0]       = hi2(v.x, v.y);
    base[lane * 2 + 1]       = hi2(v.z, v.w);
    base[128 + lane * 2 + 0] = lo2(v.x, v.y);
    base[128 + lane * 2 + 1] = lo2(v.z, v.w);
    if (lane < 16) {
        float4 qv = ((const float4*)(q + (size_t)row * Q_DIM))[lane];
        base[64 + lane * 2 + 0]  = hi2(qv.x, qv.y);
        base[64 + lane * 2 + 1]  = hi2(qv.z, qv.w);
        base[192 + lane * 2 + 0] = lo2(qv.x, qv.y);
        base[192 + lane * 2 + 1] = lo2(qv.z, qv.w);
    }
    // zero pad cols 192..255 in both segments (graph col patched in mlp0 smem)
    base[96 + lane]  = __nv_bfloat162(__float2bfloat16_rn(0.0f), __float2bfloat16_rn(0.0f));
    base[224 + lane] = __nv_bfloat162(__float2bfloat16_rn(0.0f), __float2bfloat16_rn(0.0f));
}

// ---------------------------------------------------------------------------
// Kernel 2: symmetric gram-count, bf16 HMMA, triangular grid, cp.async loads.
// (unchanged, proven)
// ---------------------------------------------------------------------------
#define GRAM_SMEM_DYN 65536

__global__ void __launch_bounds__(256) gram_mma_kernel() {
    int bid = blockIdx.x;
    int bi = 0, rem = bid;
    while (rem >= 64 - bi) { rem -= 64 - bi; bi++; }
    int bj = bi + rem;
    const bool diag = (bi == bj);

    extern __shared__ char smem[];
    int t = threadIdx.x, wid = t >> 5, lane = t & 31;
    int warp_m = wid >> 2, warp_n = wid & 3;
    int rowBase = bi * 128;
    int colBase = bj * 128;

    uint32_t sA = smem_u32(smem);
    uint32_t sB = sA + 32768;

    #pragma unroll
    for (int l = 0; l < 8; l++) {
        int u = t + l * 256;
        int row = u >> 4, seg = u & 15;
        uint32_t off = SWZ256((uint32_t)row * 256 + seg * 16);
        cp_async16(sA + off, (const char*)g_xnb + (size_t)(rowBase + row) * 256 + seg * 16);
        cp_async16(sB + off, (const char*)g_xnb + (size_t)(colBase + row) * 256 + seg * 16);
    }
    asm volatile("cp.async.commit_group;" ::: "memory");
    asm volatile("cp.async.wait_group 0;" ::: "memory");
    __syncthreads();

    int a_row_l   = warp_m * 64 + (lane & 15);
    int a_chunk_l = lane >> 4;
    int b_row_l   = warp_n * 32 + ((lane >> 4) << 3) + (lane & 7);
    int b_chunk_l = (lane >> 3) & 1;

    float acc[4][4][4];
    #pragma unroll
    for (int mi = 0; mi < 4; mi++)
        #pragma unroll
        for (int ni = 0; ni < 4; ni++)
            #pragma unroll
            for (int r = 0; r < 4; r++) acc[mi][ni][r] = 0.0f;

    #pragma unroll
    for (int kk = 0; kk < 8; kk++) {
        uint32_t a[4][4];
        #pragma unroll
        for (int mi = 0; mi < 4; mi++) {
            uint32_t byte = (uint32_t)(a_row_l + mi * 16) * 256 + (kk * 2 + a_chunk_l) * 16;
            uint32_t addr = sA + SWZ256(byte);
            asm volatile("ldmatrix.sync.aligned.m8n8.x4.shared.b16 {%0,%1,%2,%3}, [%4];"
                         : "=r"(a[mi][0]), "=r"(a[mi][1]), "=r"(a[mi][2]), "=r"(a[mi][3])
                         : "r"(addr));
        }
        uint32_t b[4][2];
        #pragma unroll
        for (int np = 0; np < 2; np++) {
            uint32_t byte = (uint32_t)(b_row_l + np * 16) * 256 + (kk * 2 + b_chunk_l) * 16;
            uint32_t addr = sB + SWZ256(byte);
            asm volatile("ldmatrix.sync.aligned.m8n8.x4.shared.b16 {%0,%1,%2,%3}, [%4];"
                         : "=r"(b[np*2][0]), "=r"(b[np*2][1]), "=r"(b[np*2+1][0]), "=r"(b[np*2+1][1])
                         : "r"(addr));
        }
        #pragma unroll
        for (int mi = 0; mi < 4; mi++)
            #pragma unroll
            for (int ni = 0; ni < 4; ni++)
                asm volatile(
                    "mma.sync.aligned.m16n8k16.row.col.f32.bf16.bf16.f32 "
                    "{%0,%1,%2,%3}, {%4,%5,%6,%7}, {%8,%9}, {%0,%1,%2,%3};"
                    : "+f"(acc[mi][ni][0]), "+f"(acc[mi][ni][1]),
                      "+f"(acc[mi][ni][2]), "+f"(acc[mi][ni][3])
                    : "r"(a[mi][0]), "r"(a[mi][1]), "r"(a[mi][2]), "r"(a[mi][3]),
                      "r"(b[ni][0]), "r"(b[ni][1]));
    }

    int g0 = lane >> 2, q4 = lane & 3;
    #pragma unroll
    for (int mi = 0; mi < 4; mi++) {
        int row0 = rowBase + warp_m * 64 + mi * 16 + g0;
        int row1 = row0 + 8;
        #pragma unroll
        for (int ni = 0; ni < 4; ni++) {
            int c0 = colBase + warp_n * 32 + ni * 8 + q4 * 2;
            #pragma unroll
            for (int r = 0; r < 4; r++) {
                int row = (r < 2) ? row0 : row1;
                int col = c0 + (r & 1);
                float v = acc[mi][ni][r];
                if (v * v >= THRESH && row != col) {
                    atomicAdd(&g_cnt[row], 1);
                    if (!diag) atomicAdd(&g_cnt[col], 1);
                }
            }
        }
    }
}

// ---------------------------------------------------------------------------
// MLP GEMM (HMMA), cp.async 2-stage pipeline, K=768 in 6 chunks.
// MODE 0 additionally patches the graph-feature column (within-chunk col 64,
// byte 128) into the smem A tile for logical chunks 1,3 (hi) and 5 (lo).
// ---------------------------------------------------------------------------
#define MLP_SMEM_DYN 131072

template <int MODE>
__global__ void __launch_bounds__(256) mlp_mma_kernel(const float* __restrict__ bias,
                                                      const float* __restrict__ W3) {
    const __nv_bfloat16* A = (MODE == 0) ? g_fpp  : g_hpp;
    const __nv_bfloat16* W = (MODE == 0) ? g_w1pp : g_w2pp;
    const int NC = KT / 128;

    extern __shared__ char smem[];
    int t = threadIdx.x, wid = t >> 5, lane = t & 31;
    int warp_m = wid >> 2, warp_n = wid & 3;
    int mBase = blockIdx.y * 128;
    int nBase = blockIdx.x * 128;
    uint32_t sbase = smem_u32(smem);

    // graph feature for patch (MODE 0): value for this CTA's row t (t<128)
    float gval = 0.0f;
    if (MODE == 0 && t < 128) gval = (float)g_cnt[mBase + t] * (1.0f / (float)B_ROWS);

    auto load_chunk = [&](int c, int stage) {
        int ca = (c < 2) ? c : (c - 2);
        uint32_t dA = sbase + stage * 65536;
        uint32_t dW = dA + 32768;
        #pragma unroll
        for (int l = 0; l < 8; l++) {
            int u = t + l * 256;
            int row = u >> 4, seg = u & 15;
            uint32_t off = SWZ256((uint32_t)row * 256 + seg * 16);
            const char* pa = (const char*)A + (size_t)(mBase + row) * (KTA * 2) + ca * 256 + seg * 16;
            const char* pw = (const char*)W + (size_t)(nBase + row) * (KT * 2)  + c  * 256 + seg * 16;
            cp_async16(dA + off, pa);
            cp_async16(dW + off, pw);
        }
        asm volatile("cp.async.commit_group;" ::: "memory");
    };

    int a_row_l   = warp_m * 64 + (lane & 15);
    int a_chunk_l = lane >> 4;
    int b_row_l   = warp_n * 32 + ((lane >> 4) << 3) + (lane & 7);
    int b_chunk_l = (lane >> 3) & 1;

    float acc[4][4][4];
    #pragma unroll
    for (int mi = 0; mi < 4; mi++)
        #pragma unroll
        for (int ni = 0; ni < 4; ni++)
            #pragma unroll
            for (int r = 0; r < 4; r++) acc[mi][ni][r] = 0.0f;

    load_chunk(0, 0);
    for (int c = 0; c < NC; c++) {
        if (c + 1 < NC) {
            load_chunk(c + 1, (c + 1) & 1);
            asm volatile("cp.async.wait_group 1;" ::: "memory");
        } else {
            asm volatile("cp.async.wait_group 0;" ::: "memory");
        }
        __syncthreads();

        uint32_t sA = sbase + (uint32_t)(c & 1) * 65536;
        uint32_t sB = sA + 32768;

        if (MODE == 0 && (c == 1 || c == 3 || c == 5)) {
            // patch graph column: within-chunk col 64 -> byte 128 of the row
            if (t < 128) {
                __nv_bfloat16 hv = __float2bfloat16_rn(gval);
                __nv_bfloat16 val = (c == 5)
                    ? __float2bfloat16_rn(gval - __bfloat162float(hv)) : hv;
                uint32_t off = SWZ256((uint32_t)t * 256 + 128);
                *(__nv_bfloat16*)(smem + (uint32_t)(c & 1) * 65536 + off) = val;
            }
            __syncthreads();
        }

        #pragma unroll
        for (int kk = 0; kk < 8; kk++) {
            uint32_t a[4][4];
            #pragma unroll
            for (int mi = 0; mi < 4; mi++) {
                uint32_t byte = (uint32_t)(a_row_l + mi * 16) * 256 + (kk * 2 + a_chunk_l) * 16;
                uint32_t addr = sA + SWZ256(byte);
                asm volatile("ldmatrix.sync.aligned.m8n8.x4.shared.b16 {%0,%1,%2,%3}, [%4];"
                             : "=r"(a[mi][0]), "=r"(a[mi][1]), "=r"(a[mi][2]), "=r"(a[mi][3])
                             : "r"(addr));
            }
            uint32_t b[4][2];
            #pragma unroll
            for (int np = 0; np < 2; np++) {
                uint32_t byte = (uint32_t)(b_row_l + np * 16) * 256 + (kk * 2 + b_chunk_l) * 16;
                uint32_t addr = sB + SWZ256(byte);
                asm volatile("ldmatrix.sync.aligned.m8n8.x4.shared.b16 {%0,%1,%2,%3}, [%4];"
                             : "=r"(b[np*2][0]), "=r"(b[np*2][1]), "=r"(b[np*2+1][0]), "=r"(b[np*2+1][1])
                             : "r"(addr));
            }
            #pragma unroll
            for (int mi = 0; mi < 4; mi++)
                #pragma unroll
                for (int ni = 0; ni < 4; ni++)
                    asm volatile(
                        "mma.sync.aligned.m16n8k16.row.col.f32.bf16.bf16.f32 "
                        "{%0,%1,%2,%3}, {%4,%5,%6,%7}, {%8,%9}, {%0,%1,%2,%3};"
                        : "+f"(acc[mi][ni][0]), "+f"(acc[mi][ni][1]),
                          "+f"(acc[mi][ni][2]), "+f"(acc[mi][ni][3])
                        : "r"(a[mi][0]), "r"(a[mi][1]), "r"(a[mi][2]), "r"(a[mi][3]),
                          "r"(b[ni][0]), "r"(b[ni][1]));
        }
        __syncthreads();
    }

    int g0 = lane >> 2, q4 = lane & 3;
    #pragma unroll
    for (int mi = 0; mi < 4; mi++) {
        int row0 = mBase + warp_m * 64 + mi * 16 + g0;
        int row1 = row0 + 8;
        float s0 = 0.0f, s1 = 0.0f;
        #pragma unroll
        for (int ni = 0; ni < 4; ni++) {
            int col = nBase + warp_n * 32 + ni * 8 + q4 * 2;
            float bv0 = bias[col], bv1 = bias[col + 1];
            float h00 = fmaxf(acc[mi][ni][0] + bv0, 0.0f);
            float h01 = fmaxf(acc[mi][ni][1] + bv1, 0.0f);
            float h10 = fmaxf(acc[mi][ni][2] + bv0, 0.0f);
            float h11 = fmaxf(acc[mi][ni][3] + bv1, 0.0f);
            if (MODE == 0) {
                __nv_bfloat162* p0 = (__nv_bfloat162*)(g_hpp + (size_t)row0 * KTA + col);
                __nv_bfloat162* p1 = (__nv_bfloat162*)(g_hpp + (size_t)row1 * KTA + col);
                p0[0] = hi2(h00, h01); p0[128] = lo2(h00, h01);
                p1[0] = hi2(h10, h11); p1[128] = lo2(h10, h11);
            } else {
                float w0 = W3[col], w1 = W3[col + 1];
                s0 = fmaf(h00, w0, fmaf(h01, w1, s0));
                s1 = fmaf(h10, w0, fmaf(h11, w1, s1));
            }
        }
        if (MODE == 1) {
            s0 += __shfl_xor_sync(0xffffffffu, s0, 1);
            s0 += __shfl_xor_sync(0xffffffffu, s0, 2);
            s1 += __shfl_xor_sync(0xffffffffu, s1, 1);
            s1 += __shfl_xor_sync(0xffffffffu, s1, 2);
            if (q4 == 0) {
                int slot = blockIdx.x * 4 + warp_n;
                g_part[(size_t)row0 * 8 + slot] = s0;
                g_part[(size_t)row1 * 8 + slot] = s1;
            }
        }
    }
}

// ---------------------------------------------------------------------------
__global__ void finalize_kernel(const float* __restrict__ b3,
                                float* __restrict__ out) {
    int i = blockIdx.x * 256 + threadIdx.x;
    const float4* p = (const float4*)(g_part + (size_t)i * 8);
    float4 u = p[0], v = p[1];
    out[i] = ((u.x + u.y) + (u.z + u.w)) + ((v.x + v.y) + (v.z + v.w)) + b3[0];
}

// ---------------------------------------------------------------------------
extern "C" void kernel_launch(void* const* d_in, const int* in_sizes, int n_in,
                              void* d_out, int out_size) {
    const float* x  = (const float*)d_in[0];
    const float* q  = (const float*)d_in[1];
    const float* W1 = (const float*)d_in[2];
    const float* b1 = (const float*)d_in[3];
    const float* W2 = (const float*)d_in[4];
    const float* b2 = (const float*)d_in[5];
    const float* W3 = (const float*)d_in[6];
    const float* b3 = (const float*)d_in[7];
    float* out = (float*)d_out;

    cudaFuncSetAttribute(gram_mma_kernel,
                         cudaFuncAttributeMaxDynamicSharedMemorySize, GRAM_SMEM_DYN);
    cudaFuncSetAttribute(mlp_mma_kernel<0>,
                         cudaFuncAttributeMaxDynamicSharedMemorySize, MLP_SMEM_DYN);
    cudaFuncSetAttribute(mlp_mma_kernel<1>,
                         cudaFuncAttributeMaxDynamicSharedMemorySize, MLP_SMEM_DYN);

    rownorm_prepw_kernel<<<B_ROWS / 8 + 256, 256>>>(x, q, W1, W2);
    gram_mma_kernel<<<2080, 256, GRAM_SMEM_DYN>>>();
    mlp_mma_kernel<0><<<dim3(H1D / 128, B_ROWS / 128), 256, MLP_SMEM_DYN>>>(b1, W3);
    mlp_mma_kernel<1><<<dim3(H2D / 128, B_ROWS / 128), 256, MLP_SMEM_DYN>>>(b2, W3);
    finalize_kernel<<<B_ROWS / 256, 256>>>(b3, out);
}